// round 7
// baseline (speedup 1.0000x reference)
#include <cuda_runtime.h>
#include <cstdint>

// QuantumParity analytic reduction (see R1):
//   feat_k     = prod_{q=0..k}   cos(x_q)
//   feat_(i,j) = prod_{q=i+1..j} cos(x_q)
//   out[c] = b[c] + sum_f W[c][f] * feat_f
//
// R7 (= R6 with the asm-constraint compile fix): W/bias in __constant__
// memory, filled by a stage kernel + async D2D memcpy node inside the
// captured graph. Hot kernel: LDG x -> 8 cos -> packed f32x2 dot with
// constant-bank W (LDC.64, immediate offsets) -> STG. No smem, no barrier.

#define NQ 8
#define NFEAT 36

// cW[f] packs {W[0][f], W[1][f]} as two fp32 in one 64-bit word; cW[36] = bias.
__constant__ unsigned long long cW[NFEAT + 1];
__device__ unsigned long long g_stage[NFEAT + 1];

__device__ __forceinline__ unsigned long long pack2(float lo, float hi) {
    unsigned long long r;
    asm("mov.b64 %0, {%1, %2};" : "=l"(r) : "f"(lo), "f"(hi));
    return r;
}

__global__ void stage_kernel(const float* __restrict__ W,
                             const float* __restrict__ bias) {
    int t = threadIdx.x;
    if (t < NFEAT)  g_stage[t] = pack2(W[t], W[NFEAT + t]);
    if (t == NFEAT) g_stage[t] = pack2(bias[0], bias[1]);
}

__device__ __forceinline__ uint64_t pack_dup(float v) {
    uint64_t r;
    asm("mov.b64 %0, {%1, %1};" : "=l"(r) : "f"(v));
    return r;
}
__device__ __forceinline__ uint64_t fma2(uint64_t a, uint64_t b, uint64_t c) {
    uint64_t d;
    asm("fma.rn.f32x2 %0, %1, %2, %3;" : "=l"(d) : "l"(a), "l"(b), "l"(c));
    return d;
}
__device__ __forceinline__ uint64_t mul2(uint64_t a, uint64_t b) {
    uint64_t d;
    asm("mul.rn.f32x2 %0, %1, %2;" : "=l"(d) : "l"(a), "l"(b));
    return d;
}
__device__ __forceinline__ uint64_t add2(uint64_t a, uint64_t b) {
    uint64_t d;
    asm("add.rn.f32x2 %0, %1, %2;" : "=l"(d) : "l"(a), "l"(b));
    return d;
}

__device__ __forceinline__ float cos_poly(float x) {
    // x in [0, pi]; cos(x) = -sin(x - pi/2). Degree-9 Taylor, |err| < 2.8e-6.
    float t = x - 1.57079632679489662f;
    float u = t * t;
    float p = fmaf(u, 2.75573192e-6f, -1.98412698e-4f);
    p = fmaf(u, p, 8.33333333e-3f);
    p = fmaf(u, p, -1.66666667e-1f);
    p = fmaf(u, p, 1.0f);
    return -t * p;
}

__global__ void __launch_bounds__(256)
quantum_parity_kernel(const float* __restrict__ x,
                      float* __restrict__ out,
                      int nrows) {
    int row = blockIdx.x * 256 + threadIdx.x;
    int rl = row < nrows ? row : (nrows - 1);

    const float4* xp = reinterpret_cast<const float4*>(x) + (size_t)rl * 2;
    float4 a = xp[0];
    float4 d = xp[1];

    uint64_t cd[NQ];
    cd[0] = pack_dup(cos_poly(a.x));
    cd[1] = pack_dup(cos_poly(a.y));
    cd[2] = pack_dup(cos_poly(a.z));
    cd[3] = pack_dup(cos_poly(a.w));
    cd[4] = pack_dup(cos_poly(d.x));
    cd[5] = pack_dup(cos_poly(d.y));
    cd[6] = pack_dup(cos_poly(d.z));
    cd[7] = pack_dup(cos_poly(d.w));

    uint64_t accA = cW[NFEAT];   // bias pair (LDC.64, immediate offset)
    uint64_t accB = 0ull;

    // Single-Z features: prefix products.
    uint64_t p = cd[0];
    accA = fma2(cW[0], p, accA);
#pragma unroll
    for (int k = 1; k < NQ; k++) {
        p = mul2(p, cd[k]);
        if (k & 1) accB = fma2(cW[k], p, accB);
        else       accA = fma2(cW[k], p, accA);
    }

    // Pair features: window products c_{i+1}..c_j.
    int f = NQ;
#pragma unroll
    for (int i = 0; i < NQ - 1; i++) {
        uint64_t q = cd[i + 1];
        if (f & 1) accB = fma2(cW[f], q, accB);
        else       accA = fma2(cW[f], q, accA);
        f++;
#pragma unroll
        for (int j = i + 2; j < NQ; j++) {
            q = mul2(q, cd[j]);
            if (f & 1) accB = fma2(cW[f], q, accB);
            else       accA = fma2(cW[f], q, accA);
            f++;
        }
    }

    if (row < nrows)
        reinterpret_cast<uint64_t*>(out)[row] = add2(accA, accB);
}

extern "C" void kernel_launch(void* const* d_in, const int* in_sizes, int n_in,
                              void* d_out, int out_size) {
    const float* x    = (const float*)d_in[0];   // (B, 8) fp32
    const float* W    = (const float*)d_in[1];   // (2, 36) fp32
    const float* bias = (const float*)d_in[2];   // (2,) fp32

    int nrows = in_sizes[0] / NQ;                // 131072
    float* out = (float*)d_out;                  // (B, 2) fp32

    // Stage W/bias interleaved, then async D2D copy into the constant bank.
    // Both are graph-capturable; no allocation, no sync.
    stage_kernel<<<1, 64>>>(W, bias);
    void* stage_ptr = nullptr;
    cudaGetSymbolAddress(&stage_ptr, g_stage);
    cudaMemcpyToSymbolAsync(cW, stage_ptr,
                            sizeof(unsigned long long) * (NFEAT + 1), 0,
                            cudaMemcpyDeviceToDevice);

    int block = 256;
    int grid = (nrows + block - 1) / block;
    quantum_parity_kernel<<<grid, block>>>(x, out, nrows);
}

// round 8
// speedup vs baseline: 1.2214x; 1.2214x over previous
#include <cuda_runtime.h>
#include <cstdint>

// QuantumParity analytic reduction (see R1):
//   feat_k     = prod_{q=0..k}   cos(x_q)
//   feat_(i,j) = prod_{q=i+1..j} cos(x_q)
//   out[c] = b[c] + sum_f W[c][f] * feat_f
//
// R8: single kernel node (R7's 3-node graph cost ~4.5us of node latency).
// R3 shell (smem W + one barrier, x load first) + packed f32x2 cosine
// evaluation (4 packed polynomial chains for 8 cosines, sign folded into
// negated coefficients) + dual-accumulator packed dot.

#define NQ 8
#define NFEAT 36

__device__ __forceinline__ uint64_t pack2(float lo, float hi) {
    uint64_t r;
    asm("mov.b64 %0, {%1, %2};" : "=l"(r) : "f"(lo), "f"(hi));
    return r;
}
__device__ __forceinline__ uint64_t pack_dup(float v) {
    uint64_t r;
    asm("mov.b64 %0, {%1, %1};" : "=l"(r) : "f"(v));
    return r;
}
__device__ __forceinline__ void unpack2(float& lo, float& hi, uint64_t v) {
    asm("mov.b64 {%0, %1}, %2;" : "=f"(lo), "=f"(hi) : "l"(v));
}
__device__ __forceinline__ uint64_t fma2(uint64_t a, uint64_t b, uint64_t c) {
    uint64_t d;
    asm("fma.rn.f32x2 %0, %1, %2, %3;" : "=l"(d) : "l"(a), "l"(b), "l"(c));
    return d;
}
__device__ __forceinline__ uint64_t mul2(uint64_t a, uint64_t b) {
    uint64_t d;
    asm("mul.rn.f32x2 %0, %1, %2;" : "=l"(d) : "l"(a), "l"(b));
    return d;
}
__device__ __forceinline__ uint64_t add2(uint64_t a, uint64_t b) {
    uint64_t d;
    asm("add.rn.f32x2 %0, %1, %2;" : "=l"(d) : "l"(a), "l"(b));
    return d;
}
__device__ __forceinline__ uint64_t lds64(uint32_t addr) {
    uint64_t d;
    asm("ld.shared.b64 %0, [%1];" : "=l"(d) : "r"(addr));
    return d;
}

// Packed cosine pair: given xx = {xa, xb} (each in [0, pi]), returns
// {cos xa, cos xb}. cos(x) = -sin(t), t = x - pi/2; the minus sign is folded
// into negated Taylor coefficients so the tail is a single mul2.
// |err| < 2.8e-6 (degree-9).
__device__ __forceinline__ uint64_t cos2(uint64_t xx) {
    const uint64_t mHPI = pack_dup(-1.57079632679489662f);
    const uint64_t K9   = pack_dup(-2.75573192e-6f);
    const uint64_t K7   = pack_dup( 1.98412698e-4f);
    const uint64_t K5   = pack_dup(-8.33333333e-3f);
    const uint64_t K3   = pack_dup( 1.66666667e-1f);
    const uint64_t K1   = pack_dup(-1.0f);
    uint64_t t = add2(xx, mHPI);
    uint64_t u = mul2(t, t);
    uint64_t p = fma2(u, K9, K7);
    p = fma2(u, p, K5);
    p = fma2(u, p, K3);
    p = fma2(u, p, K1);
    return mul2(t, p);
}

__global__ void __launch_bounds__(256)
quantum_parity_kernel(const float* __restrict__ x,
                      const float* __restrict__ W,
                      const float* __restrict__ bias,
                      float* __restrict__ out,
                      int nrows) {
    __shared__ uint64_t sW[NFEAT + 1];  // sW[f] = {W0[f], W1[f]}; sW[36] = bias
    int tid = threadIdx.x;
    int row = blockIdx.x * 256 + tid;
    int rl = row < nrows ? row : (nrows - 1);

    // x load first: DRAM latency starts immediately.
    const float4* xp = reinterpret_cast<const float4*>(x) + (size_t)rl * 2;
    float4 a = xp[0];
    float4 d = xp[1];

    // W/bias -> shared, in flight during the packed cos math below.
    if (tid <= NFEAT) {
        float lo, hi;
        if (tid < NFEAT) { lo = W[tid];  hi = W[NFEAT + tid]; }
        else             { lo = bias[0]; hi = bias[1]; }
        sW[tid] = pack2(lo, hi);
    }

    // 8 cosines via 4 packed chains, then unpack + duplicate per value.
    uint64_t c01 = cos2(pack2(a.x, a.y));
    uint64_t c23 = cos2(pack2(a.z, a.w));
    uint64_t c45 = cos2(pack2(d.x, d.y));
    uint64_t c67 = cos2(pack2(d.z, d.w));

    float v0, v1, v2, v3, v4, v5, v6, v7;
    unpack2(v0, v1, c01);
    unpack2(v2, v3, c23);
    unpack2(v4, v5, c45);
    unpack2(v6, v7, c67);

    uint64_t cd[NQ];
    cd[0] = pack_dup(v0);
    cd[1] = pack_dup(v1);
    cd[2] = pack_dup(v2);
    cd[3] = pack_dup(v3);
    cd[4] = pack_dup(v4);
    cd[5] = pack_dup(v5);
    cd[6] = pack_dup(v6);
    cd[7] = pack_dup(v7);

    __syncthreads();

    uint32_t sbase = (uint32_t)__cvta_generic_to_shared(sW);

    uint64_t accA = lds64(sbase + NFEAT * 8);  // bias pair
    uint64_t accB = 0ull;

    // Single-Z features: prefix products.
    uint64_t p = cd[0];
    accA = fma2(lds64(sbase + 0), p, accA);
#pragma unroll
    for (int k = 1; k < NQ; k++) {
        p = mul2(p, cd[k]);
        if (k & 1) accB = fma2(lds64(sbase + k * 8), p, accB);
        else       accA = fma2(lds64(sbase + k * 8), p, accA);
    }

    // Pair features: window products c_{i+1}..c_j.
    int f = NQ;
#pragma unroll
    for (int i = 0; i < NQ - 1; i++) {
        uint64_t q = cd[i + 1];
        if (f & 1) accB = fma2(lds64(sbase + f * 8), q, accB);
        else       accA = fma2(lds64(sbase + f * 8), q, accA);
        f++;
#pragma unroll
        for (int j = i + 2; j < NQ; j++) {
            q = mul2(q, cd[j]);
            if (f & 1) accB = fma2(lds64(sbase + f * 8), q, accB);
            else       accA = fma2(lds64(sbase + f * 8), q, accA);
            f++;
        }
    }

    if (row < nrows)
        reinterpret_cast<uint64_t*>(out)[row] = add2(accA, accB);
}

extern "C" void kernel_launch(void* const* d_in, const int* in_sizes, int n_in,
                              void* d_out, int out_size) {
    const float* x    = (const float*)d_in[0];   // (B, 8) fp32
    const float* W    = (const float*)d_in[1];   // (2, 36) fp32
    const float* bias = (const float*)d_in[2];   // (2,) fp32

    int nrows = in_sizes[0] / NQ;                // 131072
    float* out = (float*)d_out;                  // (B, 2) fp32

    int block = 256;
    int grid = (nrows + block - 1) / block;      // 512
    quantum_parity_kernel<<<grid, block>>>(x, W, bias, out, nrows);
}

// round 9
// speedup vs baseline: 1.6442x; 1.3462x over previous
#include <cuda_runtime.h>
#include <cstdint>

// QuantumParity analytic reduction (see R1):
//   feat_k     = prod_{q=0..k}   cos(x_q)
//   feat_(i,j) = prod_{q=i+1..j} cos(x_q)
//   out[c] = b[c] + sum_f W[c][f] * feat_f
//
// R9: R3 shell (scalar deg-9 cos, smem W, one barrier, 1 row/thread, single
// kernel node) + Horner-factored dot product:
//   sum_j w_{i,j} prod_{q=i+1..j} c_q
//     = c_{i+1} * (w_{i,i+1} + c_{i+2}*(w_{i,i+2} + ...))
// eliminating all 28 window-product muls: the dot is exactly 37 fma2 + 37 LDS.

#define NQ 8
#define NFEAT 36

__device__ __forceinline__ uint64_t pack2(float lo, float hi) {
    uint64_t r;
    asm("mov.b64 %0, {%1, %2};" : "=l"(r) : "f"(lo), "f"(hi));
    return r;
}
__device__ __forceinline__ uint64_t pack_dup(float v) {
    uint64_t r;
    asm("mov.b64 %0, {%1, %1};" : "=l"(r) : "f"(v));
    return r;
}
__device__ __forceinline__ uint64_t fma2(uint64_t a, uint64_t b, uint64_t c) {
    uint64_t d;
    asm("fma.rn.f32x2 %0, %1, %2, %3;" : "=l"(d) : "l"(a), "l"(b), "l"(c));
    return d;
}
__device__ __forceinline__ uint64_t add2(uint64_t a, uint64_t b) {
    uint64_t d;
    asm("add.rn.f32x2 %0, %1, %2;" : "=l"(d) : "l"(a), "l"(b));
    return d;
}
__device__ __forceinline__ uint64_t lds64(uint32_t addr) {
    uint64_t d;
    asm("ld.shared.b64 %0, [%1];" : "=l"(d) : "r"(addr));
    return d;
}

__device__ __forceinline__ float cos_poly(float x) {
    // x in [0, pi]; cos(x) = -sin(x - pi/2). Degree-9 Taylor, |err| < 2.8e-6.
    float t = x - 1.57079632679489662f;
    float u = t * t;
    float p = fmaf(u, 2.75573192e-6f, -1.98412698e-4f);
    p = fmaf(u, p, 8.33333333e-3f);
    p = fmaf(u, p, -1.66666667e-1f);
    p = fmaf(u, p, 1.0f);
    return -t * p;
}

__global__ void __launch_bounds__(256)
quantum_parity_kernel(const float* __restrict__ x,
                      const float* __restrict__ W,
                      const float* __restrict__ bias,
                      float* __restrict__ out,
                      int nrows) {
    __shared__ uint64_t sW[NFEAT + 1];  // sW[f] = {W0[f], W1[f]}; sW[36] = bias
    int tid = threadIdx.x;
    int row = blockIdx.x * 256 + tid;
    int rl = row < nrows ? row : (nrows - 1);

    // x load first: DRAM latency starts immediately.
    const float4* xp = reinterpret_cast<const float4*>(x) + (size_t)rl * 2;
    float4 a = xp[0];
    float4 d = xp[1];

    // W/bias -> shared, in flight during the cos math below.
    if (tid <= NFEAT) {
        float lo, hi;
        if (tid < NFEAT) { lo = W[tid];  hi = W[NFEAT + tid]; }
        else             { lo = bias[0]; hi = bias[1]; }
        sW[tid] = pack2(lo, hi);
    }

    // 8 scalar cosines, duplicated into both f32x2 lanes.
    uint64_t cd[NQ];
    cd[0] = pack_dup(cos_poly(a.x));
    cd[1] = pack_dup(cos_poly(a.y));
    cd[2] = pack_dup(cos_poly(a.z));
    cd[3] = pack_dup(cos_poly(a.w));
    cd[4] = pack_dup(cos_poly(d.x));
    cd[5] = pack_dup(cos_poly(d.y));
    cd[6] = pack_dup(cos_poly(d.z));
    cd[7] = pack_dup(cos_poly(d.w));

    __syncthreads();

    uint32_t sbase = (uint32_t)__cvta_generic_to_shared(sW);

    uint64_t acc0 = lds64(sbase + NFEAT * 8);  // bias pair
    uint64_t acc1 = 0ull;

    // Single-Z chain (ranges starting at q=0, weights sW[0..7]):
    //   sum_k u_k * prod_{q=0..k} c_q
    //     = c0*(u0 + c1*(u1 + ... c7*(u7)))
    {
        uint64_t h = lds64(sbase + 7 * 8);
#pragma unroll
        for (int k = 6; k >= 0; k--)
            h = fma2(cd[k + 1], h, lds64(sbase + k * 8));
        acc0 = fma2(cd[0], h, acc0);
    }

    // Pair chains: for each i, features (i,j) = prod_{q=i+1..j} c_q,
    // weights at f = 8 + i*7 - i*(i-1)/2 + (j-i-1).
#pragma unroll
    for (int i = 0; i < NQ - 1; i++) {
        const int off = 8 + i * 7 - (i * (i - 1)) / 2;
        uint64_t h = lds64(sbase + (off + 6 - i) * 8);   // w(i,7)
#pragma unroll
        for (int j = 6; j >= i + 1; j--)
            h = fma2(cd[j + 1], h, lds64(sbase + (off + j - i - 1) * 8));
        if (i & 1) acc1 = fma2(cd[i + 1], h, acc1);
        else       acc0 = fma2(cd[i + 1], h, acc0);
    }

    if (row < nrows)
        reinterpret_cast<uint64_t*>(out)[row] = add2(acc0, acc1);
}

extern "C" void kernel_launch(void* const* d_in, const int* in_sizes, int n_in,
                              void* d_out, int out_size) {
    const float* x    = (const float*)d_in[0];   // (B, 8) fp32
    const float* W    = (const float*)d_in[1];   // (2, 36) fp32
    const float* bias = (const float*)d_in[2];   // (2,) fp32

    int nrows = in_sizes[0] / NQ;                // 131072
    float* out = (float*)d_out;                  // (B, 2) fp32

    int block = 256;
    int grid = (nrows + block - 1) / block;      // 512
    quantum_parity_kernel<<<grid, block>>>(x, W, bias, out, nrows);
}